// round 1
// baseline (speedup 1.0000x reference)
#include <cuda_runtime.h>
#include <math.h>

#define B_  4
#define SQ_ 2048
#define SK_ 2048
#define D_  1024
#define H_  16
#define HD_ 64

// Scratch (allocation-free contract: __device__ globals)
__device__ float g_q[B_ * SQ_ * D_];
__device__ float g_k[B_ * SK_ * D_];
__device__ float g_v[B_ * SK_ * D_];
__device__ float g_attn[B_ * SQ_ * D_];

// ---------------------------------------------------------------------------
// GEMM: C[M,N] = A[M,K] @ W[N,K]^T + bias[N]   (torch Linear layout)
// 64x64 block tile, BK=32, 256 threads, 4x4 micro-tile.
// ---------------------------------------------------------------------------
#define BM 64
#define BN 64
#define BKC 32

__global__ __launch_bounds__(256) void gemm_bias(
    const float* __restrict__ A, const float* __restrict__ W,
    const float* __restrict__ bias, float* __restrict__ C,
    int M, int N, int K)
{
    __shared__ float As[BM][BKC + 4];
    __shared__ float Ws[BN][BKC + 4];

    const int tid = threadIdx.x;
    const int m0 = blockIdx.y * BM;
    const int n0 = blockIdx.x * BN;
    const int tr = tid >> 4;        // 0..15
    const int tc = tid & 15;        // 0..15

    const int lr = tid >> 3;        // 0..31
    const int lc = (tid & 7) * 4;   // 0..28

    float acc[4][4] = {};

    for (int k0 = 0; k0 < K; k0 += BKC) {
        *(float4*)&As[lr][lc]      = *(const float4*)&A[(size_t)(m0 + lr) * K + k0 + lc];
        *(float4*)&As[lr + 32][lc] = *(const float4*)&A[(size_t)(m0 + lr + 32) * K + k0 + lc];
        *(float4*)&Ws[lr][lc]      = *(const float4*)&W[(size_t)(n0 + lr) * K + k0 + lc];
        *(float4*)&Ws[lr + 32][lc] = *(const float4*)&W[(size_t)(n0 + lr + 32) * K + k0 + lc];
        __syncthreads();

        #pragma unroll
        for (int d4 = 0; d4 < BKC / 4; d4++) {
            float4 a[4], b[4];
            #pragma unroll
            for (int i = 0; i < 4; i++) a[i] = *(float4*)&As[tr * 4 + i][d4 * 4];
            #pragma unroll
            for (int j = 0; j < 4; j++) b[j] = *(float4*)&Ws[tc * 4 + j][d4 * 4];
            #pragma unroll
            for (int i = 0; i < 4; i++)
                #pragma unroll
                for (int j = 0; j < 4; j++)
                    acc[i][j] += a[i].x * b[j].x + a[i].y * b[j].y
                               + a[i].z * b[j].z + a[i].w * b[j].w;
        }
        __syncthreads();
    }

    #pragma unroll
    for (int i = 0; i < 4; i++) {
        #pragma unroll
        for (int j = 0; j < 4; j++) {
            int n = n0 + tc * 4 + j;
            C[(size_t)(m0 + tr * 4 + i) * N + n] = acc[i][j] + bias[n];
        }
    }
}

// ---------------------------------------------------------------------------
// Flash attention (fp32, causal via provided additive mask, online softmax)
// Block: one (b, h, 64-row q tile). 256 threads, 4x4 micro-tiles.
// ---------------------------------------------------------------------------
#define FP 68          // smem row pitch (floats), 16B aligned, conflict-limiting
#define FLASH_SMEM (4 * 64 * FP * 4)

__global__ __launch_bounds__(256) void flash_kernel(
    const float* __restrict__ Q, const float* __restrict__ Kg,
    const float* __restrict__ Vg, const float* __restrict__ mask,
    const unsigned char* __restrict__ kpm, float* __restrict__ O)
{
    extern __shared__ float smem[];
    float (*Qs)[FP] = (float(*)[FP])(smem);
    float (*Ks)[FP] = (float(*)[FP])(smem + 64 * FP);
    float (*Vs)[FP] = (float(*)[FP])(smem + 2 * 64 * FP);
    float (*Ps)[FP] = (float(*)[FP])(smem + 3 * 64 * FP);

    const int qi = blockIdx.x;
    const int h  = blockIdx.y;
    const int b  = blockIdx.z;
    const int q0 = qi * 64;

    const int tid = threadIdx.x;
    const int tr = tid >> 4;   // 0..15
    const int tc = tid & 15;   // 0..15

    const int lrow = tid >> 4;       // 0..15
    const int lcol = (tid & 15) * 4; // 0..60

    // Load Q tile [64][64]
    const float* Qbase = Q + ((size_t)b * SQ_ + q0) * D_ + h * HD_;
    #pragma unroll
    for (int i = 0; i < 4; i++) {
        int r = lrow + 16 * i;
        *(float4*)&Qs[r][lcol] = *(const float4*)&Qbase[(size_t)r * D_ + lcol];
    }
    __syncthreads();

    float m[4], l[4], o[4][4];
    #pragma unroll
    for (int i = 0; i < 4; i++) {
        m[i] = -INFINITY; l[i] = 0.f;
        #pragma unroll
        for (int j = 0; j < 4; j++) o[i][j] = 0.f;
    }

    const float scale = 0.125f;  // 1/sqrt(64)

    for (int kt = 0; kt <= qi; kt++) {   // causal: skip fully-masked tiles
        const int k0 = kt * 64;
        const float* Kbase = Kg + ((size_t)b * SK_ + k0) * D_ + h * HD_;
        const float* Vbase = Vg + ((size_t)b * SK_ + k0) * D_ + h * HD_;
        #pragma unroll
        for (int i = 0; i < 4; i++) {
            int r = lrow + 16 * i;
            *(float4*)&Ks[r][lcol] = *(const float4*)&Kbase[(size_t)r * D_ + lcol];
            *(float4*)&Vs[r][lcol] = *(const float4*)&Vbase[(size_t)r * D_ + lcol];
        }
        __syncthreads();

        // S = Q K^T
        float s[4][4] = {};
        #pragma unroll
        for (int d4 = 0; d4 < 16; d4++) {
            float4 a[4], bb[4];
            #pragma unroll
            for (int i = 0; i < 4; i++) a[i]  = *(float4*)&Qs[tr * 4 + i][d4 * 4];
            #pragma unroll
            for (int j = 0; j < 4; j++) bb[j] = *(float4*)&Ks[tc * 4 + j][d4 * 4];
            #pragma unroll
            for (int i = 0; i < 4; i++)
                #pragma unroll
                for (int j = 0; j < 4; j++)
                    s[i][j] += a[i].x * bb[j].x + a[i].y * bb[j].y
                             + a[i].z * bb[j].z + a[i].w * bb[j].w;
        }

        // scale + additive mask + key padding
        #pragma unroll
        for (int i = 0; i < 4; i++) {
            int qrow = q0 + tr * 4 + i;
            #pragma unroll
            for (int j = 0; j < 4; j++) {
                int kcol = k0 + tc * 4 + j;
                float sv = s[i][j] * scale + mask[(size_t)qrow * SK_ + kcol];
                if (kpm[(size_t)b * SK_ + kcol]) sv = -INFINITY;
                s[i][j] = sv;
            }
        }

        // online softmax: row reductions over the 16 lanes sharing tr
        #pragma unroll
        for (int i = 0; i < 4; i++) {
            float v = fmaxf(fmaxf(s[i][0], s[i][1]), fmaxf(s[i][2], s[i][3]));
            #pragma unroll
            for (int off = 8; off >= 1; off >>= 1)
                v = fmaxf(v, __shfl_xor_sync(0xffffffffu, v, off));
            float mn = fmaxf(m[i], v);
            float corr = expf(m[i] - mn);
            m[i] = mn;

            float rs = 0.f;
            #pragma unroll
            for (int j = 0; j < 4; j++) {
                s[i][j] = expf(s[i][j] - mn);
                rs += s[i][j];
            }
            #pragma unroll
            for (int off = 8; off >= 1; off >>= 1)
                rs += __shfl_xor_sync(0xffffffffu, rs, off);

            l[i] = l[i] * corr + rs;
            #pragma unroll
            for (int j = 0; j < 4; j++) o[i][j] *= corr;

            *(float4*)&Ps[tr * 4 + i][tc * 4] =
                make_float4(s[i][0], s[i][1], s[i][2], s[i][3]);
        }
        __syncthreads();

        // O += P @ V
        #pragma unroll 16
        for (int kk = 0; kk < 64; kk++) {
            float4 vb = *(float4*)&Vs[kk][tc * 4];
            #pragma unroll
            for (int i = 0; i < 4; i++) {
                float pv = Ps[tr * 4 + i][kk];
                o[i][0] += pv * vb.x;
                o[i][1] += pv * vb.y;
                o[i][2] += pv * vb.z;
                o[i][3] += pv * vb.w;
            }
        }
        __syncthreads();
    }

    // epilogue: normalize and write
    float* Obase = O + ((size_t)b * SQ_ + q0) * D_ + h * HD_;
    #pragma unroll
    for (int i = 0; i < 4; i++) {
        float inv = 1.f / l[i];
        float4 w = make_float4(o[i][0] * inv, o[i][1] * inv,
                               o[i][2] * inv, o[i][3] * inv);
        *(float4*)&Obase[(size_t)(tr * 4 + i) * D_ + tc * 4] = w;
    }
}

// ---------------------------------------------------------------------------
extern "C" void kernel_launch(void* const* d_in, const int* in_sizes, int n_in,
                              void* d_out, int out_size)
{
    const float* query = (const float*)d_in[0];
    const float* key   = (const float*)d_in[1];
    const float* value = (const float*)d_in[2];
    const float* amask = (const float*)d_in[3];
    const unsigned char* kpm = (const unsigned char*)d_in[4];
    const float* Wq = (const float*)d_in[5];
    const float* bq = (const float*)d_in[6];
    const float* Wk = (const float*)d_in[7];
    const float* bk = (const float*)d_in[8];
    const float* Wv = (const float*)d_in[9];
    const float* bv = (const float*)d_in[10];
    const float* Wo = (const float*)d_in[11];
    const float* bo = (const float*)d_in[12];
    float* out = (float*)d_out;

    float *q, *k, *v, *attn;
    cudaGetSymbolAddress((void**)&q,    g_q);
    cudaGetSymbolAddress((void**)&k,    g_k);
    cudaGetSymbolAddress((void**)&v,    g_v);
    cudaGetSymbolAddress((void**)&attn, g_attn);

    const int M = B_ * SQ_;
    dim3 ggrid(D_ / BN, M / BM);

    gemm_bias<<<ggrid, 256>>>(query, Wq, bq, q, M, D_, D_);
    gemm_bias<<<ggrid, 256>>>(key,   Wk, bk, k, M, D_, D_);
    gemm_bias<<<ggrid, 256>>>(value, Wv, bv, v, M, D_, D_);

    cudaFuncSetAttribute(flash_kernel,
                         cudaFuncAttributeMaxDynamicSharedMemorySize, FLASH_SMEM);
    flash_kernel<<<dim3(SQ_ / 64, H_, B_), 256, FLASH_SMEM>>>(
        q, k, v, amask, kpm, attn);

    gemm_bias<<<ggrid, 256>>>(attn, Wo, bo, out, M, D_, D_);
}

// round 3
// speedup vs baseline: 2.2090x; 2.2090x over previous
#include <cuda_runtime.h>
#include <math.h>

#define B_  4
#define SQ_ 2048
#define SK_ 2048
#define D_  1024
#define H_  16
#define HD_ 64

// Scratch (allocation-free contract: __device__ globals)
__device__ float g_q[B_ * SQ_ * D_];
__device__ float g_k[B_ * SK_ * D_];
__device__ float g_v[B_ * SK_ * D_];
__device__ float g_attn[B_ * SQ_ * D_];

// ---------------------------------------------------------------------------
// tf32 mma.sync helpers
// ---------------------------------------------------------------------------
__device__ __forceinline__ void mma_tf32(float* d, const unsigned* a, const unsigned* b) {
    asm volatile(
        "mma.sync.aligned.m16n8k8.row.col.f32.tf32.tf32.f32 "
        "{%0,%1,%2,%3},{%4,%5,%6,%7},{%8,%9},{%0,%1,%2,%3};\n"
        : "+f"(d[0]), "+f"(d[1]), "+f"(d[2]), "+f"(d[3])
        : "r"(a[0]), "r"(a[1]), "r"(a[2]), "r"(a[3]), "r"(b[0]), "r"(b[1]));
}

// fp32 -> (tf32_hi, tf32_lo) split: x ≈ hi + lo, residual ~2^-22 |x|
__device__ __forceinline__ void f2tf32x2(float x, unsigned& hi, unsigned& lo) {
    asm("cvt.rn.tf32.f32 %0, %1;" : "=r"(hi) : "f"(x));
    float r = x - __uint_as_float(hi);
    asm("cvt.rn.tf32.f32 %0, %1;" : "=r"(lo) : "f"(r));
}

__device__ __forceinline__ void cp16(void* smem, const void* g) {
    unsigned s = (unsigned)__cvta_generic_to_shared(smem);
    asm volatile("cp.async.cg.shared.global [%0], [%1], 16;\n" :: "r"(s), "l"(g));
}
__device__ __forceinline__ void cp_commit() {
    asm volatile("cp.async.commit_group;\n" ::);
}
__device__ __forceinline__ void cp_wait0() {
    asm volatile("cp.async.wait_group 0;\n" ::);
}

// ---------------------------------------------------------------------------
// tf32x3 tensor-core GEMM: C[M,N] = A[M,K] @ W[N,K]^T + bias[N]
// Block tile 256x128, BK=32, 256 threads (8 warps, 64x64 per warp),
// double-buffered cp.async. Each fp32 operand split into hi+lo tf32;
// acc += Ah*Bh + Ah*Bl + Al*Bh  (error ~1e-7, vs 1.2e-3 for raw truncation).
// ---------------------------------------------------------------------------
#define GTM 256
#define GTN 128
#define GTK 32
#define GP  36   // smem row pitch (floats): 144B, 16B-aligned, conflict-free frags

#define GEMM_SMEM ((2 * GTM * GP + 2 * GTN * GP) * 4)

__global__ __launch_bounds__(256, 1) void gemm_tf32(
    const float* __restrict__ A, const float* __restrict__ W,
    const float* __restrict__ bias, float* __restrict__ C,
    int M, int N, int K)
{
    extern __shared__ float sm[];
    float* As = sm;                    // 2 stages of GTM x GP
    float* Bs = sm + 2 * GTM * GP;     // 2 stages of GTN x GP

    const int tid  = threadIdx.x;
    const int m0   = blockIdx.y * GTM;
    const int n0   = blockIdx.x * GTN;
    const int warp = tid >> 5, lane = tid & 31;
    const int wm   = warp >> 1, wn = warp & 1;   // 4 x 2 warp grid
    const int g    = lane >> 2, tg = lane & 3;

    float acc[4][8][4];
    #pragma unroll
    for (int i = 0; i < 4; i++)
        #pragma unroll
        for (int j = 0; j < 8; j++)
            #pragma unroll
            for (int q = 0; q < 4; q++) acc[i][j][q] = 0.f;

    const int nk = K / GTK;

    // --- stage 0 prefetch ---
    {
        #pragma unroll
        for (int i = 0; i < 8; i++) {
            int c = tid + i * 256;
            int row = c >> 3, col = (c & 7) * 4;
            cp16(&As[row * GP + col], &A[(size_t)(m0 + row) * K + col]);
        }
        #pragma unroll
        for (int i = 0; i < 4; i++) {
            int c = tid + i * 256;
            int row = c >> 3, col = (c & 7) * 4;
            cp16(&Bs[row * GP + col], &W[(size_t)(n0 + row) * K + col]);
        }
        cp_commit();
    }

    for (int kt = 0; kt < nk; kt++) {
        cp_wait0();
        __syncthreads();

        if (kt + 1 < nk) {
            const int s  = (kt + 1) & 1;
            const int k0 = (kt + 1) * GTK;
            float* Ad = As + s * GTM * GP;
            float* Bd = Bs + s * GTN * GP;
            #pragma unroll
            for (int i = 0; i < 8; i++) {
                int c = tid + i * 256;
                int row = c >> 3, col = (c & 7) * 4;
                cp16(&Ad[row * GP + col], &A[(size_t)(m0 + row) * K + k0 + col]);
            }
            #pragma unroll
            for (int i = 0; i < 4; i++) {
                int c = tid + i * 256;
                int row = c >> 3, col = (c & 7) * 4;
                cp16(&Bd[row * GP + col], &W[(size_t)(n0 + row) * K + k0 + col]);
            }
            cp_commit();
        }

        // --- compute on buffer kt&1 ---
        const float* Ab = As + (kt & 1) * GTM * GP;
        const float* Bb = Bs + (kt & 1) * GTN * GP;

        #pragma unroll
        for (int ks = 0; ks < 4; ks++) {
            const int kc = ks * 8 + tg;
            unsigned ah[4][4], al[4][4], bh[8][2], bl[8][2];
            #pragma unroll
            for (int mf = 0; mf < 4; mf++) {
                const float* p = Ab + (wm * 64 + mf * 16 + g) * GP + kc;
                f2tf32x2(p[0],           ah[mf][0], al[mf][0]);
                f2tf32x2(p[8 * GP],      ah[mf][1], al[mf][1]);
                f2tf32x2(p[4],           ah[mf][2], al[mf][2]);
                f2tf32x2(p[8 * GP + 4],  ah[mf][3], al[mf][3]);
            }
            #pragma unroll
            for (int nf = 0; nf < 8; nf++) {
                const float* p = Bb + (wn * 64 + nf * 8 + g) * GP + kc;
                f2tf32x2(p[0], bh[nf][0], bl[nf][0]);
                f2tf32x2(p[4], bh[nf][1], bl[nf][1]);
            }
            #pragma unroll
            for (int mf = 0; mf < 4; mf++)
                #pragma unroll
                for (int nf = 0; nf < 8; nf++) {
                    mma_tf32(acc[mf][nf], ah[mf], bl[nf]);
                    mma_tf32(acc[mf][nf], al[mf], bh[nf]);
                    mma_tf32(acc[mf][nf], ah[mf], bh[nf]);
                }
        }
        __syncthreads();
    }

    // --- epilogue: bias + store ---
    #pragma unroll
    for (int mf = 0; mf < 4; mf++) {
        #pragma unroll
        for (int nf = 0; nf < 8; nf++) {
            int row = m0 + wm * 64 + mf * 16 + g;
            int col = n0 + wn * 64 + nf * 8 + tg * 2;
            float b0 = bias[col], b1 = bias[col + 1];
            float2 v0 = make_float2(acc[mf][nf][0] + b0, acc[mf][nf][1] + b1);
            float2 v1 = make_float2(acc[mf][nf][2] + b0, acc[mf][nf][3] + b1);
            *(float2*)&C[(size_t)row * N + col]       = v0;
            *(float2*)&C[(size_t)(row + 8) * N + col] = v1;
        }
    }
}

// ---------------------------------------------------------------------------
// Flash attention (fp32, arithmetic causal mask, online softmax)
// Block: one (b, h, 64-row q tile). 256 threads, 4x4 micro-tiles.
// ---------------------------------------------------------------------------
#define FP 68
#define FLASH_SMEM (4 * 64 * FP * 4)

__global__ __launch_bounds__(256) void flash_kernel(
    const float* __restrict__ Q, const float* __restrict__ Kg,
    const float* __restrict__ Vg, float* __restrict__ O)
{
    extern __shared__ float smem[];
    float (*Qs)[FP] = (float(*)[FP])(smem);
    float (*Ks)[FP] = (float(*)[FP])(smem + 64 * FP);
    float (*Vs)[FP] = (float(*)[FP])(smem + 2 * 64 * FP);
    float (*Ps)[FP] = (float(*)[FP])(smem + 3 * 64 * FP);

    const int qi = blockIdx.x;
    const int h  = blockIdx.y;
    const int b  = blockIdx.z;
    const int q0 = qi * 64;

    const int tid = threadIdx.x;
    const int tr = tid >> 4;
    const int tc = tid & 15;

    const int lrow = tid >> 4;
    const int lcol = (tid & 15) * 4;

    const float* Qbase = Q + ((size_t)b * SQ_ + q0) * D_ + h * HD_;
    #pragma unroll
    for (int i = 0; i < 4; i++) {
        int r = lrow + 16 * i;
        *(float4*)&Qs[r][lcol] = *(const float4*)&Qbase[(size_t)r * D_ + lcol];
    }
    __syncthreads();

    float m[4], l[4], o[4][4];
    #pragma unroll
    for (int i = 0; i < 4; i++) {
        m[i] = -INFINITY; l[i] = 0.f;
        #pragma unroll
        for (int j = 0; j < 4; j++) o[i][j] = 0.f;
    }

    const float scale = 0.125f;

    for (int kt = 0; kt <= qi; kt++) {
        const int k0 = kt * 64;
        const float* Kbase = Kg + ((size_t)b * SK_ + k0) * D_ + h * HD_;
        const float* Vbase = Vg + ((size_t)b * SK_ + k0) * D_ + h * HD_;
        #pragma unroll
        for (int i = 0; i < 4; i++) {
            int r = lrow + 16 * i;
            *(float4*)&Ks[r][lcol] = *(const float4*)&Kbase[(size_t)r * D_ + lcol];
            *(float4*)&Vs[r][lcol] = *(const float4*)&Vbase[(size_t)r * D_ + lcol];
        }
        __syncthreads();

        float s[4][4] = {};
        #pragma unroll
        for (int d4 = 0; d4 < 16; d4++) {
            float4 a[4], bb[4];
            #pragma unroll
            for (int i = 0; i < 4; i++) a[i]  = *(float4*)&Qs[tr * 4 + i][d4 * 4];
            #pragma unroll
            for (int j = 0; j < 4; j++) bb[j] = *(float4*)&Ks[tc * 4 + j][d4 * 4];
            #pragma unroll
            for (int i = 0; i < 4; i++)
                #pragma unroll
                for (int j = 0; j < 4; j++)
                    s[i][j] += a[i].x * bb[j].x + a[i].y * bb[j].y
                             + a[i].z * bb[j].z + a[i].w * bb[j].w;
        }

        // scale + arithmetic causal mask (reference mask is tril ? 0 : -1e9)
        if (kt == qi) {
            #pragma unroll
            for (int i = 0; i < 4; i++) {
                int qrow = tr * 4 + i;
                #pragma unroll
                for (int j = 0; j < 4; j++) {
                    int kcol = tc * 4 + j;
                    s[i][j] = s[i][j] * scale + (kcol <= qrow ? 0.f : -1e9f);
                }
            }
        } else {
            #pragma unroll
            for (int i = 0; i < 4; i++)
                #pragma unroll
                for (int j = 0; j < 4; j++)
                    s[i][j] *= scale;
        }

        #pragma unroll
        for (int i = 0; i < 4; i++) {
            float v = fmaxf(fmaxf(s[i][0], s[i][1]), fmaxf(s[i][2], s[i][3]));
            #pragma unroll
            for (int off = 8; off >= 1; off >>= 1)
                v = fmaxf(v, __shfl_xor_sync(0xffffffffu, v, off));
            float mn = fmaxf(m[i], v);
            float corr = __expf(m[i] - mn);
            m[i] = mn;

            float rs = 0.f;
            #pragma unroll
            for (int j = 0; j < 4; j++) {
                s[i][j] = __expf(s[i][j] - mn);
                rs += s[i][j];
            }
            #pragma unroll
            for (int off = 8; off >= 1; off >>= 1)
                rs += __shfl_xor_sync(0xffffffffu, rs, off);

            l[i] = l[i] * corr + rs;
            #pragma unroll
            for (int j = 0; j < 4; j++) o[i][j] *= corr;

            *(float4*)&Ps[tr * 4 + i][tc * 4] =
                make_float4(s[i][0], s[i][1], s[i][2], s[i][3]);
        }
        __syncthreads();

        #pragma unroll 16
        for (int kk = 0; kk < 64; kk++) {
            float4 vb = *(float4*)&Vs[kk][tc * 4];
            #pragma unroll
            for (int i = 0; i < 4; i++) {
                float pv = Ps[tr * 4 + i][kk];
                o[i][0] += pv * vb.x;
                o[i][1] += pv * vb.y;
                o[i][2] += pv * vb.z;
                o[i][3] += pv * vb.w;
            }
        }
        __syncthreads();
    }

    float* Obase = O + ((size_t)b * SQ_ + q0) * D_ + h * HD_;
    #pragma unroll
    for (int i = 0; i < 4; i++) {
        float inv = 1.f / l[i];
        float4 w = make_float4(o[i][0] * inv, o[i][1] * inv,
                               o[i][2] * inv, o[i][3] * inv);
        *(float4*)&Obase[(size_t)(tr * 4 + i) * D_ + tc * 4] = w;
    }
}

// ---------------------------------------------------------------------------
extern "C" void kernel_launch(void* const* d_in, const int* in_sizes, int n_in,
                              void* d_out, int out_size)
{
    const float* query = (const float*)d_in[0];
    const float* key   = (const float*)d_in[1];
    const float* value = (const float*)d_in[2];
    const float* Wq = (const float*)d_in[5];
    const float* bq = (const float*)d_in[6];
    const float* Wk = (const float*)d_in[7];
    const float* bk = (const float*)d_in[8];
    const float* Wv = (const float*)d_in[9];
    const float* bv = (const float*)d_in[10];
    const float* Wo = (const float*)d_in[11];
    const float* bo = (const float*)d_in[12];
    float* out = (float*)d_out;

    float *q, *k, *v, *attn;
    cudaGetSymbolAddress((void**)&q,    g_q);
    cudaGetSymbolAddress((void**)&k,    g_k);
    cudaGetSymbolAddress((void**)&v,    g_v);
    cudaGetSymbolAddress((void**)&attn, g_attn);

    const int M = B_ * SQ_;

    static int attr_done = 0;
    if (!attr_done) {
        cudaFuncSetAttribute(gemm_tf32,
                             cudaFuncAttributeMaxDynamicSharedMemorySize, GEMM_SMEM);
        cudaFuncSetAttribute(flash_kernel,
                             cudaFuncAttributeMaxDynamicSharedMemorySize, FLASH_SMEM);
        attr_done = 1;
    }

    dim3 ggrid(D_ / GTN, M / GTM);   // (8, 32)

    gemm_tf32<<<ggrid, 256, GEMM_SMEM>>>(query, Wq, bq, q, M, D_, D_);
    gemm_tf32<<<ggrid, 256, GEMM_SMEM>>>(key,   Wk, bk, k, M, D_, D_);
    gemm_tf32<<<ggrid, 256, GEMM_SMEM>>>(value, Wv, bv, v, M, D_, D_);

    flash_kernel<<<dim3(SQ_ / 64, H_, B_), 256, FLASH_SMEM>>>(q, k, v, attn);

    gemm_tf32<<<ggrid, 256, GEMM_SMEM>>>(attn, Wo, bo, out, M, D_, D_);
}

// round 6
// speedup vs baseline: 3.3664x; 1.5240x over previous
#include <cuda_runtime.h>
#include <math.h>

#define B_  4
#define SQ_ 2048
#define SK_ 2048
#define D_  1024
#define H_  16
#define HD_ 64

// Scratch (allocation-free contract: __device__ globals)
__device__ float g_q[B_ * SQ_ * D_];
__device__ float g_k[B_ * SK_ * D_];
__device__ float g_v[B_ * SK_ * D_];
__device__ float g_attn[B_ * SQ_ * D_];

// ---------------------------------------------------------------------------
// tf32 mma.sync helpers
// ---------------------------------------------------------------------------
__device__ __forceinline__ void mma_tf32(float* d, const unsigned* a, const unsigned* b) {
    asm volatile(
        "mma.sync.aligned.m16n8k8.row.col.f32.tf32.tf32.f32 "
        "{%0,%1,%2,%3},{%4,%5,%6,%7},{%8,%9},{%0,%1,%2,%3};\n"
        : "+f"(d[0]), "+f"(d[1]), "+f"(d[2]), "+f"(d[3])
        : "r"(a[0]), "r"(a[1]), "r"(a[2]), "r"(a[3]), "r"(b[0]), "r"(b[1]));
}

// fp32 -> (tf32_hi, tf32_lo) split: x ≈ hi + lo, residual ~2^-22 |x|
__device__ __forceinline__ void f2tf32x2(float x, unsigned& hi, unsigned& lo) {
    asm("cvt.rn.tf32.f32 %0, %1;" : "=r"(hi) : "f"(x));
    float r = x - __uint_as_float(hi);
    asm("cvt.rn.tf32.f32 %0, %1;" : "=r"(lo) : "f"(r));
}

__device__ __forceinline__ void cp16(void* smem, const void* g) {
    unsigned s = (unsigned)__cvta_generic_to_shared(smem);
    asm volatile("cp.async.cg.shared.global [%0], [%1], 16;\n" :: "r"(s), "l"(g));
}
__device__ __forceinline__ void cp_commit() {
    asm volatile("cp.async.commit_group;\n" ::);
}
__device__ __forceinline__ void cp_wait0() {
    asm volatile("cp.async.wait_group 0;\n" ::);
}

// ---------------------------------------------------------------------------
// tf32x3 tensor-core GEMM: C[M,N] = A[M,K] @ W[N,K]^T + bias[N]
// ---------------------------------------------------------------------------
#define GTM 256
#define GTN 128
#define GTK 32
#define GP  36

#define GEMM_SMEM ((2 * GTM * GP + 2 * GTN * GP) * 4)

__global__ __launch_bounds__(256, 1) void gemm_tf32(
    const float* __restrict__ A, const float* __restrict__ W,
    const float* __restrict__ bias, float* __restrict__ C,
    int M, int N, int K)
{
    extern __shared__ float sm[];
    float* As = sm;
    float* Bs = sm + 2 * GTM * GP;

    const int tid  = threadIdx.x;
    const int m0   = blockIdx.y * GTM;
    const int n0   = blockIdx.x * GTN;
    const int warp = tid >> 5, lane = tid & 31;
    const int wm   = warp >> 1, wn = warp & 1;
    const int g    = lane >> 2, tg = lane & 3;

    float acc[4][8][4];
    #pragma unroll
    for (int i = 0; i < 4; i++)
        #pragma unroll
        for (int j = 0; j < 8; j++)
            #pragma unroll
            for (int q = 0; q < 4; q++) acc[i][j][q] = 0.f;

    const int nk = K / GTK;

    {
        #pragma unroll
        for (int i = 0; i < 8; i++) {
            int c = tid + i * 256;
            int row = c >> 3, col = (c & 7) * 4;
            cp16(&As[row * GP + col], &A[(size_t)(m0 + row) * K + col]);
        }
        #pragma unroll
        for (int i = 0; i < 4; i++) {
            int c = tid + i * 256;
            int row = c >> 3, col = (c & 7) * 4;
            cp16(&Bs[row * GP + col], &W[(size_t)(n0 + row) * K + col]);
        }
        cp_commit();
    }

    for (int kt = 0; kt < nk; kt++) {
        cp_wait0();
        __syncthreads();

        if (kt + 1 < nk) {
            const int s  = (kt + 1) & 1;
            const int k0 = (kt + 1) * GTK;
            float* Ad = As + s * GTM * GP;
            float* Bd = Bs + s * GTN * GP;
            #pragma unroll
            for (int i = 0; i < 8; i++) {
                int c = tid + i * 256;
                int row = c >> 3, col = (c & 7) * 4;
                cp16(&Ad[row * GP + col], &A[(size_t)(m0 + row) * K + k0 + col]);
            }
            #pragma unroll
            for (int i = 0; i < 4; i++) {
                int c = tid + i * 256;
                int row = c >> 3, col = (c & 7) * 4;
                cp16(&Bd[row * GP + col], &W[(size_t)(n0 + row) * K + k0 + col]);
            }
            cp_commit();
        }

        const float* Ab = As + (kt & 1) * GTM * GP;
        const float* Bb = Bs + (kt & 1) * GTN * GP;

        #pragma unroll
        for (int ks = 0; ks < 4; ks++) {
            const int kc = ks * 8 + tg;
            unsigned ah[4][4], al[4][4], bh[8][2], bl[8][2];
            #pragma unroll
            for (int mf = 0; mf < 4; mf++) {
                const float* p = Ab + (wm * 64 + mf * 16 + g) * GP + kc;
                f2tf32x2(p[0],           ah[mf][0], al[mf][0]);
                f2tf32x2(p[8 * GP],      ah[mf][1], al[mf][1]);
                f2tf32x2(p[4],           ah[mf][2], al[mf][2]);
                f2tf32x2(p[8 * GP + 4],  ah[mf][3], al[mf][3]);
            }
            #pragma unroll
            for (int nf = 0; nf < 8; nf++) {
                const float* p = Bb + (wn * 64 + nf * 8 + g) * GP + kc;
                f2tf32x2(p[0], bh[nf][0], bl[nf][0]);
                f2tf32x2(p[4], bh[nf][1], bl[nf][1]);
            }
            #pragma unroll
            for (int mf = 0; mf < 4; mf++)
                #pragma unroll
                for (int nf = 0; nf < 8; nf++) {
                    mma_tf32(acc[mf][nf], ah[mf], bl[nf]);
                    mma_tf32(acc[mf][nf], al[mf], bh[nf]);
                    mma_tf32(acc[mf][nf], ah[mf], bh[nf]);
                }
        }
        __syncthreads();
    }

    #pragma unroll
    for (int mf = 0; mf < 4; mf++) {
        #pragma unroll
        for (int nf = 0; nf < 8; nf++) {
            int row = m0 + wm * 64 + mf * 16 + g;
            int col = n0 + wn * 64 + nf * 8 + tg * 2;
            float b0 = bias[col], b1 = bias[col + 1];
            float2 v0 = make_float2(acc[mf][nf][0] + b0, acc[mf][nf][1] + b1);
            float2 v1 = make_float2(acc[mf][nf][2] + b0, acc[mf][nf][3] + b1);
            *(float2*)&C[(size_t)row * N + col]       = v0;
            *(float2*)&C[(size_t)(row + 8) * N + col] = v1;
        }
    }
}

// ---------------------------------------------------------------------------
// Tensor-core flash attention (tf32x3 for QK^T and PV, online softmax).
// Block: (b, h, 64-row q tile), 128 threads / 4 warps, 16 q-rows per warp.
// Q/K/P smem pitch 68 (conflict-free 4g+tg frag reads);
// V pitch 72 (conflict-free 8tg+g B-frag reads).
// ---------------------------------------------------------------------------
#define FQP 68
#define FVP 72
#define Q_OFF 0
#define K_OFF (64 * FQP)
#define P_OFF (2 * 64 * FQP)
#define V_OFF (3 * 64 * FQP)
#define FLASH_SMEM ((3 * 64 * FQP + 64 * FVP) * 4)

__global__ __launch_bounds__(128) void flash_tc(
    const float* __restrict__ Q, const float* __restrict__ Kg,
    const float* __restrict__ Vg, float* __restrict__ O)
{
    extern __shared__ float smem[];
    float* Qs = smem + Q_OFF;
    float* Ks = smem + K_OFF;
    float* Ps = smem + P_OFF;
    float* Vs = smem + V_OFF;

    const int qi = blockIdx.x;
    const int h  = blockIdx.y;
    const int b  = blockIdx.z;
    const int q0 = qi * 64;

    const int tid  = threadIdx.x;
    const int warp = tid >> 5, lane = tid & 31;
    const int g = lane >> 2, tg = lane & 3;

    const int lr = tid >> 4;          // 0..7
    const int lc = (tid & 15) * 4;    // 0..60

    // Load Q tile [64][64], pre-scaled by 1/sqrt(HD)
    const float* Qbase = Q + ((size_t)b * SQ_ + q0) * D_ + h * HD_;
    #pragma unroll
    for (int it = 0; it < 8; it++) {
        int r = lr + it * 8;
        float4 qv = *(const float4*)&Qbase[(size_t)r * D_ + lc];
        qv.x *= 0.125f; qv.y *= 0.125f; qv.z *= 0.125f; qv.w *= 0.125f;
        *(float4*)&Qs[r * FQP + lc] = qv;
    }

    float m0 = -INFINITY, m1 = -INFINITY, l0 = 0.f, l1 = 0.f;
    float o[8][4];
    #pragma unroll
    for (int nf = 0; nf < 8; nf++)
        #pragma unroll
        for (int j = 0; j < 4; j++) o[nf][j] = 0.f;

    for (int kt = 0; kt <= qi; kt++) {
        const int k0 = kt * 64;
        __syncthreads();   // all warps done with previous K/V/P
        const float* Kbase = Kg + ((size_t)b * SK_ + k0) * D_ + h * HD_;
        const float* Vbase = Vg + ((size_t)b * SK_ + k0) * D_ + h * HD_;
        #pragma unroll
        for (int it = 0; it < 8; it++) {
            int r = lr + it * 8;
            *(float4*)&Ks[r * FQP + lc] = *(const float4*)&Kbase[(size_t)r * D_ + lc];
            *(float4*)&Vs[r * FVP + lc] = *(const float4*)&Vbase[(size_t)r * D_ + lc];
        }
        __syncthreads();

        // ---- S = Q K^T (tf32x3), warp computes rows [warp*16, warp*16+16) ----
        float c[8][4];
        #pragma unroll
        for (int nf = 0; nf < 8; nf++)
            #pragma unroll
            for (int j = 0; j < 4; j++) c[nf][j] = 0.f;

        #pragma unroll
        for (int ks = 0; ks < 8; ks++) {
            const int kc = ks * 8 + tg;
            unsigned ah[4], al[4], bh[8][2], bl[8][2];
            const float* p = Qs + (warp * 16 + g) * FQP + kc;
            f2tf32x2(p[0],            ah[0], al[0]);
            f2tf32x2(p[8 * FQP],      ah[1], al[1]);
            f2tf32x2(p[4],            ah[2], al[2]);
            f2tf32x2(p[8 * FQP + 4],  ah[3], al[3]);
            #pragma unroll
            for (int nf = 0; nf < 8; nf++) {
                const float* pb = Ks + (nf * 8 + g) * FQP + kc;
                f2tf32x2(pb[0], bh[nf][0], bl[nf][0]);
                f2tf32x2(pb[4], bh[nf][1], bl[nf][1]);
            }
            #pragma unroll
            for (int nf = 0; nf < 8; nf++) {
                mma_tf32(c[nf], ah, bl[nf]);
                mma_tf32(c[nf], al, bh[nf]);
                mma_tf32(c[nf], ah, bh[nf]);
            }
        }

        // ---- causal mask on diagonal tile ----
        if (kt == qi) {
            const int r0 = warp * 16 + g, r1 = r0 + 8;
            #pragma unroll
            for (int nf = 0; nf < 8; nf++) {
                int col0 = nf * 8 + tg * 2, col1 = col0 + 1;
                if (col0 > r0) c[nf][0] = -1e9f;
                if (col1 > r0) c[nf][1] = -1e9f;
                if (col0 > r1) c[nf][2] = -1e9f;
                if (col1 > r1) c[nf][3] = -1e9f;
            }
        }

        // ---- online softmax (rows g and g+8 of this warp's 16) ----
        float rx0 = -INFINITY, rx1 = -INFINITY;
        #pragma unroll
        for (int nf = 0; nf < 8; nf++) {
            rx0 = fmaxf(rx0, fmaxf(c[nf][0], c[nf][1]));
            rx1 = fmaxf(rx1, fmaxf(c[nf][2], c[nf][3]));
        }
        #pragma unroll
        for (int off = 1; off <= 2; off <<= 1) {
            rx0 = fmaxf(rx0, __shfl_xor_sync(0xffffffffu, rx0, off));
            rx1 = fmaxf(rx1, __shfl_xor_sync(0xffffffffu, rx1, off));
        }
        float mn0 = fmaxf(m0, rx0), mn1 = fmaxf(m1, rx1);
        float corr0 = __expf(m0 - mn0), corr1 = __expf(m1 - mn1);
        m0 = mn0; m1 = mn1;

        float rs0 = 0.f, rs1 = 0.f;
        #pragma unroll
        for (int nf = 0; nf < 8; nf++) {
            c[nf][0] = __expf(c[nf][0] - mn0);
            c[nf][1] = __expf(c[nf][1] - mn0);
            c[nf][2] = __expf(c[nf][2] - mn1);
            c[nf][3] = __expf(c[nf][3] - mn1);
            rs0 += c[nf][0] + c[nf][1];
            rs1 += c[nf][2] + c[nf][3];
            // store P fragment to smem (warp-private rows)
            *(float2*)&Ps[(warp * 16 + g) * FQP + nf * 8 + tg * 2] =
                make_float2(c[nf][0], c[nf][1]);
            *(float2*)&Ps[(warp * 16 + g + 8) * FQP + nf * 8 + tg * 2] =
                make_float2(c[nf][2], c[nf][3]);
        }
        #pragma unroll
        for (int off = 1; off <= 2; off <<= 1) {
            rs0 += __shfl_xor_sync(0xffffffffu, rs0, off);
            rs1 += __shfl_xor_sync(0xffffffffu, rs1, off);
        }
        l0 = l0 * corr0 + rs0;
        l1 = l1 * corr1 + rs1;
        #pragma unroll
        for (int nf = 0; nf < 8; nf++) {
            o[nf][0] *= corr0; o[nf][1] *= corr0;
            o[nf][2] *= corr1; o[nf][3] *= corr1;
        }
        __syncwarp();

        // ---- O += P V (tf32x3) ----
        #pragma unroll
        for (int ks = 0; ks < 8; ks++) {
            const int kc = ks * 8 + tg;
            unsigned ah[4], al[4], bh[8][2], bl[8][2];
            const float* p = Ps + (warp * 16 + g) * FQP + kc;
            f2tf32x2(p[0],            ah[0], al[0]);
            f2tf32x2(p[8 * FQP],      ah[1], al[1]);
            f2tf32x2(p[4],            ah[2], al[2]);
            f2tf32x2(p[8 * FQP + 4],  ah[3], al[3]);
            #pragma unroll
            for (int nf = 0; nf < 8; nf++) {
                const float* pb = Vs + (ks * 8 + tg) * FVP + nf * 8 + g;
                f2tf32x2(pb[0],       bh[nf][0], bl[nf][0]);
                f2tf32x2(pb[4 * FVP], bh[nf][1], bl[nf][1]);
            }
            #pragma unroll
            for (int nf = 0; nf < 8; nf++) {
                mma_tf32(o[nf], ah, bl[nf]);
                mma_tf32(o[nf], al, bh[nf]);
                mma_tf32(o[nf], ah, bh[nf]);
            }
        }
    }

    // ---- epilogue ----
    float inv0 = 1.f / l0, inv1 = 1.f / l1;
    float* Obase = O + ((size_t)b * SQ_ + q0 + warp * 16 + g) * D_ + h * HD_;
    #pragma unroll
    for (int nf = 0; nf < 8; nf++) {
        int col = nf * 8 + tg * 2;
        *(float2*)&Obase[col] =
            make_float2(o[nf][0] * inv0, o[nf][1] * inv0);
        *(float2*)&Obase[(size_t)8 * D_ + col] =
            make_float2(o[nf][2] * inv1, o[nf][3] * inv1);
    }
}

// ---------------------------------------------------------------------------
extern "C" void kernel_launch(void* const* d_in, const int* in_sizes, int n_in,
                              void* d_out, int out_size)
{
    const float* query = (const float*)d_in[0];
    const float* key   = (const float*)d_in[1];
    const float* value = (const float*)d_in[2];
    const float* Wq = (const float*)d_in[5];
    const float* bq = (const float*)d_in[6];
    const float* Wk = (const float*)d_in[7];
    const float* bk = (const float*)d_in[8];
    const float* Wv = (const float*)d_in[9];
    const float* bv = (const float*)d_in[10];
    const float* Wo = (const float*)d_in[11];
    const float* bo = (const float*)d_in[12];
    float* out = (float*)d_out;

    float *q, *k, *v, *attn;
    cudaGetSymbolAddress((void**)&q,    g_q);
    cudaGetSymbolAddress((void**)&k,    g_k);
    cudaGetSymbolAddress((void**)&v,    g_v);
    cudaGetSymbolAddress((void**)&attn, g_attn);

    const int M = B_ * SQ_;

    static int attr_done = 0;
    if (!attr_done) {
        cudaFuncSetAttribute(gemm_tf32,
                             cudaFuncAttributeMaxDynamicSharedMemorySize, GEMM_SMEM);
        cudaFuncSetAttribute(flash_tc,
                             cudaFuncAttributeMaxDynamicSharedMemorySize, FLASH_SMEM);
        attr_done = 1;
    }

    dim3 ggrid(D_ / GTN, M / GTM);

    gemm_tf32<<<ggrid, 256, GEMM_SMEM>>>(query, Wq, bq, q, M, D_, D_);
    gemm_tf32<<<ggrid, 256, GEMM_SMEM>>>(key,   Wk, bk, k, M, D_, D_);
    gemm_tf32<<<ggrid, 256, GEMM_SMEM>>>(value, Wv, bv, v, M, D_, D_);

    flash_tc<<<dim3(SQ_ / 64, H_, B_), 128, FLASH_SMEM>>>(q, k, v, attn);

    gemm_tf32<<<ggrid, 256, GEMM_SMEM>>>(attn, Wo, bo, out, M, D_, D_);
}

// round 7
// speedup vs baseline: 4.2583x; 1.2649x over previous
#include <cuda_runtime.h>
#include <cuda_bf16.h>
#include <math.h>

#define B_  4
#define SQ_ 2048
#define SK_ 2048
#define D_  1024
#define H_  16
#define HD_ 64

// Scratch (allocation-free contract: __device__ globals)
__device__ float g_q[B_ * SQ_ * D_];
__device__ float g_k[B_ * SK_ * D_];
__device__ float g_v[B_ * SK_ * D_];
__device__ float g_attn[B_ * SQ_ * D_];
// bf16 hi/lo planes (reused across the sequential GEMMs)
__device__ __nv_bfloat16 g_xh[B_ * SQ_ * D_];
__device__ __nv_bfloat16 g_xl[B_ * SQ_ * D_];
__device__ __nv_bfloat16 g_wh[D_ * D_];
__device__ __nv_bfloat16 g_wl[D_ * D_];

// ---------------------------------------------------------------------------
// mma helpers
// ---------------------------------------------------------------------------
__device__ __forceinline__ void mma_tf32(float* d, const unsigned* a, const unsigned* b) {
    asm volatile(
        "mma.sync.aligned.m16n8k8.row.col.f32.tf32.tf32.f32 "
        "{%0,%1,%2,%3},{%4,%5,%6,%7},{%8,%9},{%0,%1,%2,%3};\n"
        : "+f"(d[0]), "+f"(d[1]), "+f"(d[2]), "+f"(d[3])
        : "r"(a[0]), "r"(a[1]), "r"(a[2]), "r"(a[3]), "r"(b[0]), "r"(b[1]));
}

__device__ __forceinline__ void mma_bf16(float* d, const unsigned* a, const unsigned* b) {
    asm volatile(
        "mma.sync.aligned.m16n8k16.row.col.f32.bf16.bf16.f32 "
        "{%0,%1,%2,%3},{%4,%5,%6,%7},{%8,%9},{%0,%1,%2,%3};\n"
        : "+f"(d[0]), "+f"(d[1]), "+f"(d[2]), "+f"(d[3])
        : "r"(a[0]), "r"(a[1]), "r"(a[2]), "r"(a[3]), "r"(b[0]), "r"(b[1]));
}

// fp32 -> (tf32_hi, tf32_lo) split (flash kernel only)
__device__ __forceinline__ void f2tf32x2(float x, unsigned& hi, unsigned& lo) {
    asm("cvt.rn.tf32.f32 %0, %1;" : "=r"(hi) : "f"(x));
    float r = x - __uint_as_float(hi);
    asm("cvt.rn.tf32.f32 %0, %1;" : "=r"(lo) : "f"(r));
}

__device__ __forceinline__ void cp16(void* smem, const void* g) {
    unsigned s = (unsigned)__cvta_generic_to_shared(smem);
    asm volatile("cp.async.cg.shared.global [%0], [%1], 16;\n" :: "r"(s), "l"(g));
}
__device__ __forceinline__ void cp_commit() {
    asm volatile("cp.async.commit_group;\n" ::);
}
__device__ __forceinline__ void cp_wait0() {
    asm volatile("cp.async.wait_group 0;\n" ::);
}

// ---------------------------------------------------------------------------
// Split kernel: fp32 -> bf16 hi/lo planes (x = hi + lo + O(2^-18 x))
// ---------------------------------------------------------------------------
__global__ __launch_bounds__(256) void split_kernel(
    const float* __restrict__ in, __nv_bfloat16* __restrict__ hi,
    __nv_bfloat16* __restrict__ lo, int n)
{
    int i = (blockIdx.x * 256 + threadIdx.x) * 4;
    if (i >= n) return;
    float4 x = *(const float4*)&in[i];
    __nv_bfloat162 h01 = __floats2bfloat162_rn(x.x, x.y);
    __nv_bfloat162 h23 = __floats2bfloat162_rn(x.z, x.w);
    float2 f01 = __bfloat1622float2(h01);
    float2 f23 = __bfloat1622float2(h23);
    __nv_bfloat162 l01 = __floats2bfloat162_rn(x.x - f01.x, x.y - f01.y);
    __nv_bfloat162 l23 = __floats2bfloat162_rn(x.z - f23.x, x.w - f23.y);
    *(__nv_bfloat162*)&hi[i]     = h01;
    *(__nv_bfloat162*)&hi[i + 2] = h23;
    *(__nv_bfloat162*)&lo[i]     = l01;
    *(__nv_bfloat162*)&lo[i + 2] = l23;
}

// ---------------------------------------------------------------------------
// bf16x3 tensor-core GEMM: C[M,N] = A[M,K] @ W[N,K]^T + bias[N]
// A and W pre-split into bf16 hi/lo planes. Block tile 256x128, BK=32,
// 256 threads (8 warps, 64x64 per warp), double-buffered cp.async.
// smem plane pitch = 20 words (40 bf16): frag addr 20g+tg covers all 32 banks.
// ---------------------------------------------------------------------------
#define GTM 256
#define GTN 128
#define GTK 32
#define GKP 20   // words (4B) per row per plane

#define GEMMB_SMEM ((4 * GTM * GKP + 4 * GTN * GKP) * 4)

__global__ __launch_bounds__(256, 1) void gemm_bf16x3(
    const __nv_bfloat16* __restrict__ Ah, const __nv_bfloat16* __restrict__ Al,
    const __nv_bfloat16* __restrict__ Wh, const __nv_bfloat16* __restrict__ Wl,
    const float* __restrict__ bias, float* __restrict__ C,
    int M, int N, int K)
{
    extern __shared__ unsigned smu[];
    unsigned* Ahs = smu;                                   // 2 stages GTM x GKP
    unsigned* Als = smu + 2 * GTM * GKP;
    unsigned* Bhs = smu + 4 * GTM * GKP;                   // 2 stages GTN x GKP
    unsigned* Bls = smu + 4 * GTM * GKP + 2 * GTN * GKP;

    const int tid  = threadIdx.x;
    const int m0   = blockIdx.y * GTM;
    const int n0   = blockIdx.x * GTN;
    const int warp = tid >> 5, lane = tid & 31;
    const int wm   = warp >> 1, wn = warp & 1;
    const int g    = lane >> 2, tg = lane & 3;

    float acc[4][8][4];
    #pragma unroll
    for (int i = 0; i < 4; i++)
        #pragma unroll
        for (int j = 0; j < 8; j++)
            #pragma unroll
            for (int q = 0; q < 4; q++) acc[i][j][q] = 0.f;

    const int nk = K / GTK;

    // loader mapping: c -> row = c>>2, 16B chunk = (c&3)*8 bf16
    const int lrow = tid >> 2;
    const int lch  = (tid & 3) * 8;

    // --- stage 0 prefetch ---
    {
        #pragma unroll
        for (int i = 0; i < 4; i++) {
            int row = lrow + i * 64;
            unsigned w = row * GKP + (lch >> 1);
            cp16(&Ahs[w], &Ah[(size_t)(m0 + row) * K + lch]);
            cp16(&Als[w], &Al[(size_t)(m0 + row) * K + lch]);
        }
        #pragma unroll
        for (int i = 0; i < 2; i++) {
            int row = lrow + i * 64;
            unsigned w = row * GKP + (lch >> 1);
            cp16(&Bhs[w], &Wh[(size_t)(n0 + row) * K + lch]);
            cp16(&Bls[w], &Wl[(size_t)(n0 + row) * K + lch]);
        }
        cp_commit();
    }

    for (int kt = 0; kt < nk; kt++) {
        cp_wait0();
        __syncthreads();

        if (kt + 1 < nk) {
            const int s  = (kt + 1) & 1;
            const int k0 = (kt + 1) * GTK;
            unsigned* Ahd = Ahs + s * GTM * GKP;
            unsigned* Ald = Als + s * GTM * GKP;
            unsigned* Bhd = Bhs + s * GTN * GKP;
            unsigned* Bld = Bls + s * GTN * GKP;
            #pragma unroll
            for (int i = 0; i < 4; i++) {
                int row = lrow + i * 64;
                unsigned w = row * GKP + (lch >> 1);
                cp16(&Ahd[w], &Ah[(size_t)(m0 + row) * K + k0 + lch]);
                cp16(&Ald[w], &Al[(size_t)(m0 + row) * K + k0 + lch]);
            }
            #pragma unroll
            for (int i = 0; i < 2; i++) {
                int row = lrow + i * 64;
                unsigned w = row * GKP + (lch >> 1);
                cp16(&Bhd[w], &Wh[(size_t)(n0 + row) * K + k0 + lch]);
                cp16(&Bld[w], &Wl[(size_t)(n0 + row) * K + k0 + lch]);
            }
            cp_commit();
        }

        const unsigned* Ahb = Ahs + (kt & 1) * GTM * GKP;
        const unsigned* Alb = Als + (kt & 1) * GTM * GKP;
        const unsigned* Bhb = Bhs + (kt & 1) * GTN * GKP;
        const unsigned* Blb = Bls + (kt & 1) * GTN * GKP;

        #pragma unroll
        for (int ks = 0; ks < 2; ks++) {
            const int kw = ks * 8 + tg;
            unsigned ah[4][4], al[4][4], bh[8][2], bl[8][2];
            #pragma unroll
            for (int mf = 0; mf < 4; mf++) {
                unsigned w = (wm * 64 + mf * 16 + g) * GKP + kw;
                ah[mf][0] = Ahb[w];
                ah[mf][1] = Ahb[w + 8 * GKP];
                ah[mf][2] = Ahb[w + 4];
                ah[mf][3] = Ahb[w + 8 * GKP + 4];
                al[mf][0] = Alb[w];
                al[mf][1] = Alb[w + 8 * GKP];
                al[mf][2] = Alb[w + 4];
                al[mf][3] = Alb[w + 8 * GKP + 4];
            }
            #pragma unroll
            for (int nf = 0; nf < 8; nf++) {
                unsigned w = (wn * 64 + nf * 8 + g) * GKP + kw;
                bh[nf][0] = Bhb[w];
                bh[nf][1] = Bhb[w + 4];
                bl[nf][0] = Blb[w];
                bl[nf][1] = Blb[w + 4];
            }
            #pragma unroll
            for (int mf = 0; mf < 4; mf++)
                #pragma unroll
                for (int nf = 0; nf < 8; nf++) {
                    mma_bf16(acc[mf][nf], ah[mf], bl[nf]);
                    mma_bf16(acc[mf][nf], al[mf], bh[nf]);
                    mma_bf16(acc[mf][nf], ah[mf], bh[nf]);
                }
        }
        __syncthreads();
    }

    // --- epilogue: bias + store (same accumulator layout as tf32 version) ---
    #pragma unroll
    for (int mf = 0; mf < 4; mf++) {
        #pragma unroll
        for (int nf = 0; nf < 8; nf++) {
            int row = m0 + wm * 64 + mf * 16 + g;
            int col = n0 + wn * 64 + nf * 8 + tg * 2;
            float b0 = bias[col], b1 = bias[col + 1];
            float2 v0 = make_float2(acc[mf][nf][0] + b0, acc[mf][nf][1] + b1);
            float2 v1 = make_float2(acc[mf][nf][2] + b0, acc[mf][nf][3] + b1);
            *(float2*)&C[(size_t)row * N + col]       = v0;
            *(float2*)&C[(size_t)(row + 8) * N + col] = v1;
        }
    }
}

// ---------------------------------------------------------------------------
// Tensor-core flash attention (tf32x3 for QK^T and PV, online softmax).
// Unchanged from R6 (known-good, 713us).
// ---------------------------------------------------------------------------
#define FQP 68
#define FVP 72
#define Q_OFF 0
#define K_OFF (64 * FQP)
#define P_OFF (2 * 64 * FQP)
#define V_OFF (3 * 64 * FQP)
#define FLASH_SMEM ((3 * 64 * FQP + 64 * FVP) * 4)

__global__ __launch_bounds__(128) void flash_tc(
    const float* __restrict__ Q, const float* __restrict__ Kg,
    const float* __restrict__ Vg, float* __restrict__ O)
{
    extern __shared__ float smem[];
    float* Qs = smem + Q_OFF;
    float* Ks = smem + K_OFF;
    float* Ps = smem + P_OFF;
    float* Vs = smem + V_OFF;

    const int qi = blockIdx.x;
    const int h  = blockIdx.y;
    const int b  = blockIdx.z;
    const int q0 = qi * 64;

    const int tid  = threadIdx.x;
    const int warp = tid >> 5, lane = tid & 31;
    const int g = lane >> 2, tg = lane & 3;

    const int lr = tid >> 4;
    const int lc = (tid & 15) * 4;

    const float* Qbase = Q + ((size_t)b * SQ_ + q0) * D_ + h * HD_;
    #pragma unroll
    for (int it = 0; it < 8; it++) {
        int r = lr + it * 8;
        float4 qv = *(const float4*)&Qbase[(size_t)r * D_ + lc];
        qv.x *= 0.125f; qv.y *= 0.125f; qv.z *= 0.125f; qv.w *= 0.125f;
        *(float4*)&Qs[r * FQP + lc] = qv;
    }

    float m0 = -INFINITY, m1 = -INFINITY, l0 = 0.f, l1 = 0.f;
    float o[8][4];
    #pragma unroll
    for (int nf = 0; nf < 8; nf++)
        #pragma unroll
        for (int j = 0; j < 4; j++) o[nf][j] = 0.f;

    for (int kt = 0; kt <= qi; kt++) {
        const int k0 = kt * 64;
        __syncthreads();
        const float* Kbase = Kg + ((size_t)b * SK_ + k0) * D_ + h * HD_;
        const float* Vbase = Vg + ((size_t)b * SK_ + k0) * D_ + h * HD_;
        #pragma unroll
        for (int it = 0; it < 8; it++) {
            int r = lr + it * 8;
            *(float4*)&Ks[r * FQP + lc] = *(const float4*)&Kbase[(size_t)r * D_ + lc];
            *(float4*)&Vs[r * FVP + lc] = *(const float4*)&Vbase[(size_t)r * D_ + lc];
        }
        __syncthreads();

        float c[8][4];
        #pragma unroll
        for (int nf = 0; nf < 8; nf++)
            #pragma unroll
            for (int j = 0; j < 4; j++) c[nf][j] = 0.f;

        #pragma unroll
        for (int ks = 0; ks < 8; ks++) {
            const int kc = ks * 8 + tg;
            unsigned ah[4], al[4], bh[8][2], bl[8][2];
            const float* p = Qs + (warp * 16 + g) * FQP + kc;
            f2tf32x2(p[0],            ah[0], al[0]);
            f2tf32x2(p[8 * FQP],      ah[1], al[1]);
            f2tf32x2(p[4],            ah[2], al[2]);
            f2tf32x2(p[8 * FQP + 4],  ah[3], al[3]);
            #pragma unroll
            for (int nf = 0; nf < 8; nf++) {
                const float* pb = Ks + (nf * 8 + g) * FQP + kc;
                f2tf32x2(pb[0], bh[nf][0], bl[nf][0]);
                f2tf32x2(pb[4], bh[nf][1], bl[nf][1]);
            }
            #pragma unroll
            for (int nf = 0; nf < 8; nf++) {
                mma_tf32(c[nf], ah, bl[nf]);
                mma_tf32(c[nf], al, bh[nf]);
                mma_tf32(c[nf], ah, bh[nf]);
            }
        }

        if (kt == qi) {
            const int r0 = warp * 16 + g, r1 = r0 + 8;
            #pragma unroll
            for (int nf = 0; nf < 8; nf++) {
                int col0 = nf * 8 + tg * 2, col1 = col0 + 1;
                if (col0 > r0) c[nf][0] = -1e9f;
                if (col1 > r0) c[nf][1] = -1e9f;
                if (col0 > r1) c[nf][2] = -1e9f;
                if (col1 > r1) c[nf][3] = -1e9f;
            }
        }

        float rx0 = -INFINITY, rx1 = -INFINITY;
        #pragma unroll
        for (int nf = 0; nf < 8; nf++) {
            rx0 = fmaxf(rx0, fmaxf(c[nf][0], c[nf][1]));
            rx1 = fmaxf(rx1, fmaxf(c[nf][2], c[nf][3]));
        }
        #pragma unroll
        for (int off = 1; off <= 2; off <<= 1) {
            rx0 = fmaxf(rx0, __shfl_xor_sync(0xffffffffu, rx0, off));
            rx1 = fmaxf(rx1, __shfl_xor_sync(0xffffffffu, rx1, off));
        }
        float mn0 = fmaxf(m0, rx0), mn1 = fmaxf(m1, rx1);
        float corr0 = __expf(m0 - mn0), corr1 = __expf(m1 - mn1);
        m0 = mn0; m1 = mn1;

        float rs0 = 0.f, rs1 = 0.f;
        #pragma unroll
        for (int nf = 0; nf < 8; nf++) {
            c[nf][0] = __expf(c[nf][0] - mn0);
            c[nf][1] = __expf(c[nf][1] - mn0);
            c[nf][2] = __expf(c[nf][2] - mn1);
            c[nf][3] = __expf(c[nf][3] - mn1);
            rs0 += c[nf][0] + c[nf][1];
            rs1 += c[nf][2] + c[nf][3];
            *(float2*)&Ps[(warp * 16 + g) * FQP + nf * 8 + tg * 2] =
                make_float2(c[nf][0], c[nf][1]);
            *(float2*)&Ps[(warp * 16 + g + 8) * FQP + nf * 8 + tg * 2] =
                make_float2(c[nf][2], c[nf][3]);
        }
        #pragma unroll
        for (int off = 1; off <= 2; off <<= 1) {
            rs0 += __shfl_xor_sync(0xffffffffu, rs0, off);
            rs1 += __shfl_xor_sync(0xffffffffu, rs1, off);
        }
        l0 = l0 * corr0 + rs0;
        l1 = l1 * corr1 + rs1;
        #pragma unroll
        for (int nf = 0; nf < 8; nf++) {
            o[nf][0] *= corr0; o[nf][1] *= corr0;
            o[nf][2] *= corr1; o[nf][3] *= corr1;
        }
        __syncwarp();

        #pragma unroll
        for (int ks = 0; ks < 8; ks++) {
            const int kc = ks * 8 + tg;
            unsigned ah[4], al[4], bh[8][2], bl[8][2];
            const float* p = Ps + (warp * 16 + g) * FQP + kc;
            f2tf32x2(p[0],            ah[0], al[0]);
            f2tf32x2(p[8 * FQP],      ah[1], al[1]);
            f2tf32x2(p[4],            ah[2], al[2]);
            f2tf32x2(p[8 * FQP + 4],  ah[3], al[3]);
            #pragma unroll
            for (int nf = 0; nf < 8; nf++) {
                const float* pb = Vs + (ks * 8 + tg) * FVP + nf * 8 + g;
                f2tf32x2(pb[0],       bh[nf][0], bl[nf][0]);
                f2tf32x2(pb[4 * FVP], bh[nf][1], bl[nf][1]);
            }
            #pragma unroll
            for (int nf = 0; nf < 8; nf++) {
                mma_tf32(o[nf], ah, bl[nf]);
                mma_tf32(o[nf], al, bh[nf]);
                mma_tf32(o[nf], ah, bh[nf]);
            }
        }
    }

    float inv0 = 1.f / l0, inv1 = 1.f / l1;
    float* Obase = O + ((size_t)b * SQ_ + q0 + warp * 16 + g) * D_ + h * HD_;
    #pragma unroll
    for (int nf = 0; nf < 8; nf++) {
        int col = nf * 8 + tg * 2;
        *(float2*)&Obase[col] =
            make_float2(o[nf][0] * inv0, o[nf][1] * inv0);
        *(float2*)&Obase[(size_t)8 * D_ + col] =
            make_float2(o[nf][2] * inv1, o[nf][3] * inv1);
    }
}

// ---------------------------------------------------------------------------
extern "C" void kernel_launch(void* const* d_in, const int* in_sizes, int n_in,
                              void* d_out, int out_size)
{
    const float* query = (const float*)d_in[0];
    const float* key   = (const float*)d_in[1];
    const float* value = (const float*)d_in[2];
    const float* Wq = (const float*)d_in[5];
    const float* bq = (const float*)d_in[6];
    const float* Wk = (const float*)d_in[7];
    const float* bk = (const float*)d_in[8];
    const float* Wv = (const float*)d_in[9];
    const float* bv = (const float*)d_in[10];
    const float* Wo = (const float*)d_in[11];
    const float* bo = (const float*)d_in[12];
    float* out = (float*)d_out;

    float *q, *k, *v, *attn;
    __nv_bfloat16 *xh, *xl, *wh, *wl;
    cudaGetSymbolAddress((void**)&q,    g_q);
    cudaGetSymbolAddress((void**)&k,    g_k);
    cudaGetSymbolAddress((void**)&v,    g_v);
    cudaGetSymbolAddress((void**)&attn, g_attn);
    cudaGetSymbolAddress((void**)&xh,   g_xh);
    cudaGetSymbolAddress((void**)&xl,   g_xl);
    cudaGetSymbolAddress((void**)&wh,   g_wh);
    cudaGetSymbolAddress((void**)&wl,   g_wl);

    const int M = B_ * SQ_;
    const int NX = M * D_;       // 8M activation elements
    const int NW = D_ * D_;      // 1M weight elements

    static int attr_done = 0;
    if (!attr_done) {
        cudaFuncSetAttribute(gemm_bf16x3,
                             cudaFuncAttributeMaxDynamicSharedMemorySize, GEMMB_SMEM);
        cudaFuncSetAttribute(flash_tc,
                             cudaFuncAttributeMaxDynamicSharedMemorySize, FLASH_SMEM);
        attr_done = 1;
    }

    dim3 ggrid(D_ / GTN, M / GTM);
    const int SPX = NX / 4 / 256;   // split grid for activations
    const int SPW = NW / 4 / 256;   // split grid for weights

    // Q projection
    split_kernel<<<SPX, 256>>>(query, xh, xl, NX);
    split_kernel<<<SPW, 256>>>(Wq, wh, wl, NW);
    gemm_bf16x3<<<ggrid, 256, GEMMB_SMEM>>>(xh, xl, wh, wl, bq, q, M, D_, D_);
    // K projection
    split_kernel<<<SPX, 256>>>(key, xh, xl, NX);
    split_kernel<<<SPW, 256>>>(Wk, wh, wl, NW);
    gemm_bf16x3<<<ggrid, 256, GEMMB_SMEM>>>(xh, xl, wh, wl, bk, k, M, D_, D_);
    // V projection
    split_kernel<<<SPX, 256>>>(value, xh, xl, NX);
    split_kernel<<<SPW, 256>>>(Wv, wh, wl, NW);
    gemm_bf16x3<<<ggrid, 256, GEMMB_SMEM>>>(xh, xl, wh, wl, bv, v, M, D_, D_);

    flash_tc<<<dim3(SQ_ / 64, H_, B_), 128, FLASH_SMEM>>>(q, k, v, attn);

    // Output projection
    split_kernel<<<SPX, 256>>>(attn, xh, xl, NX);
    split_kernel<<<SPW, 256>>>(Wo, wh, wl, NW);
    gemm_bf16x3<<<ggrid, 256, GEMMB_SMEM>>>(xh, xl, wh, wl, bo, out, M, D_, D_);
}

// round 8
// speedup vs baseline: 5.3724x; 1.2616x over previous
#include <cuda_runtime.h>
#include <cuda_bf16.h>
#include <math.h>

#define B_  4
#define SQ_ 2048
#define SK_ 2048
#define D_  1024
#define H_  16
#define HD_ 64

// Scratch (allocation-free contract: __device__ globals)
__device__ float g_v[B_ * SK_ * D_];
__device__ float g_attn[B_ * SQ_ * D_];
// bf16 hi/lo planes
__device__ __nv_bfloat16 g_xh[B_ * SQ_ * D_];
__device__ __nv_bfloat16 g_xl[B_ * SQ_ * D_];
__device__ __nv_bfloat16 g_wh[D_ * D_];
__device__ __nv_bfloat16 g_wl[D_ * D_];
__device__ __nv_bfloat16 g_qh[B_ * SQ_ * D_];
__device__ __nv_bfloat16 g_ql[B_ * SQ_ * D_];
__device__ __nv_bfloat16 g_kh[B_ * SK_ * D_];
__device__ __nv_bfloat16 g_kl[B_ * SK_ * D_];
__device__ __nv_bfloat16 g_vth[B_ * D_ * SK_];
__device__ __nv_bfloat16 g_vtl[B_ * D_ * SK_];

// ---------------------------------------------------------------------------
// mma helper
// ---------------------------------------------------------------------------
__device__ __forceinline__ void mma_bf16(float* d, const unsigned* a, const unsigned* b) {
    asm volatile(
        "mma.sync.aligned.m16n8k16.row.col.f32.bf16.bf16.f32 "
        "{%0,%1,%2,%3},{%4,%5,%6,%7},{%8,%9},{%0,%1,%2,%3};\n"
        : "+f"(d[0]), "+f"(d[1]), "+f"(d[2]), "+f"(d[3])
        : "r"(a[0]), "r"(a[1]), "r"(a[2]), "r"(a[3]), "r"(b[0]), "r"(b[1]));
}

__device__ __forceinline__ void cp16(void* smem, const void* g) {
    unsigned s = (unsigned)__cvta_generic_to_shared(smem);
    asm volatile("cp.async.cg.shared.global [%0], [%1], 16;\n" :: "r"(s), "l"(g));
}
__device__ __forceinline__ void cp_commit() {
    asm volatile("cp.async.commit_group;\n" ::);
}
__device__ __forceinline__ void cp_wait0() {
    asm volatile("cp.async.wait_group 0;\n" ::);
}

// ---------------------------------------------------------------------------
// Split kernel: fp32 -> bf16 hi/lo planes (x = hi + lo + O(2^-18 x))
// ---------------------------------------------------------------------------
__global__ __launch_bounds__(256) void split_kernel(
    const float* __restrict__ in, __nv_bfloat16* __restrict__ hi,
    __nv_bfloat16* __restrict__ lo, int n)
{
    int i = (blockIdx.x * 256 + threadIdx.x) * 4;
    if (i >= n) return;
    float4 x = *(const float4*)&in[i];
    __nv_bfloat162 h01 = __floats2bfloat162_rn(x.x, x.y);
    __nv_bfloat162 h23 = __floats2bfloat162_rn(x.z, x.w);
    float2 f01 = __bfloat1622float2(h01);
    float2 f23 = __bfloat1622float2(h23);
    __nv_bfloat162 l01 = __floats2bfloat162_rn(x.x - f01.x, x.y - f01.y);
    __nv_bfloat162 l23 = __floats2bfloat162_rn(x.z - f23.x, x.w - f23.y);
    *(__nv_bfloat162*)&hi[i]     = h01;
    *(__nv_bfloat162*)&hi[i + 2] = h23;
    *(__nv_bfloat162*)&lo[i]     = l01;
    *(__nv_bfloat162*)&lo[i + 2] = l23;
}

// ---------------------------------------------------------------------------
// V transpose + split: fp32 [B, SK, D] -> bf16 hi/lo planes [B, D, SK]
// ---------------------------------------------------------------------------
__global__ __launch_bounds__(256) void transpose_split(
    const float* __restrict__ V, __nv_bfloat16* __restrict__ Th,
    __nv_bfloat16* __restrict__ Tl)
{
    __shared__ float ts[32][33];
    const int d0 = blockIdx.x * 32, s0 = blockIdx.y * 32, b = blockIdx.z;
    const int tx = threadIdx.x, ty = threadIdx.y;   // (32, 8)
    #pragma unroll
    for (int i = 0; i < 4; i++) {
        int s = ty + i * 8;
        ts[s][tx] = V[((size_t)b * SK_ + s0 + s) * D_ + d0 + tx];
    }
    __syncthreads();
    #pragma unroll
    for (int i = 0; i < 4; i++) {
        int d = ty + i * 8;
        float x = ts[tx][d];
        __nv_bfloat16 hb = __float2bfloat16(x);
        float hf = __bfloat162float(hb);
        __nv_bfloat16 lb = __float2bfloat16(x - hf);
        size_t oi = ((size_t)b * D_ + d0 + d) * SK_ + s0 + tx;
        Th[oi] = hb;
        Tl[oi] = lb;
    }
}

// ---------------------------------------------------------------------------
// bf16x3 tensor-core GEMM: C = A @ W^T + bias, optional bf16 hi/lo plane out.
// mode 0: fp32 C = (acc+bias)*scale. mode 1: bf16 hi/lo planes of same.
// ---------------------------------------------------------------------------
#define GTM 256
#define GTN 128
#define GTK 32
#define GKP 20

#define GEMMB_SMEM ((4 * GTM * GKP + 4 * GTN * GKP) * 4)

__global__ __launch_bounds__(256, 1) void gemm_bf16x3(
    const __nv_bfloat16* __restrict__ Ah, const __nv_bfloat16* __restrict__ Al,
    const __nv_bfloat16* __restrict__ Wh, const __nv_bfloat16* __restrict__ Wl,
    const float* __restrict__ bias, float* __restrict__ C,
    __nv_bfloat16* __restrict__ Ch, __nv_bfloat16* __restrict__ Cl,
    float scale, int mode, int M, int N, int K)
{
    extern __shared__ unsigned smu[];
    unsigned* Ahs = smu;
    unsigned* Als = smu + 2 * GTM * GKP;
    unsigned* Bhs = smu + 4 * GTM * GKP;
    unsigned* Bls = smu + 4 * GTM * GKP + 2 * GTN * GKP;

    const int tid  = threadIdx.x;
    const int m0   = blockIdx.y * GTM;
    const int n0   = blockIdx.x * GTN;
    const int warp = tid >> 5, lane = tid & 31;
    const int wm   = warp >> 1, wn = warp & 1;
    const int g    = lane >> 2, tg = lane & 3;

    float acc[4][8][4];
    #pragma unroll
    for (int i = 0; i < 4; i++)
        #pragma unroll
        for (int j = 0; j < 8; j++)
            #pragma unroll
            for (int q = 0; q < 4; q++) acc[i][j][q] = 0.f;

    const int nk = K / GTK;
    const int lrow = tid >> 2;
    const int lch  = (tid & 3) * 8;

    {
        #pragma unroll
        for (int i = 0; i < 4; i++) {
            int row = lrow + i * 64;
            unsigned w = row * GKP + (lch >> 1);
            cp16(&Ahs[w], &Ah[(size_t)(m0 + row) * K + lch]);
            cp16(&Als[w], &Al[(size_t)(m0 + row) * K + lch]);
        }
        #pragma unroll
        for (int i = 0; i < 2; i++) {
            int row = lrow + i * 64;
            unsigned w = row * GKP + (lch >> 1);
            cp16(&Bhs[w], &Wh[(size_t)(n0 + row) * K + lch]);
            cp16(&Bls[w], &Wl[(size_t)(n0 + row) * K + lch]);
        }
        cp_commit();
    }

    for (int kt = 0; kt < nk; kt++) {
        cp_wait0();
        __syncthreads();

        if (kt + 1 < nk) {
            const int s  = (kt + 1) & 1;
            const int k0 = (kt + 1) * GTK;
            unsigned* Ahd = Ahs + s * GTM * GKP;
            unsigned* Ald = Als + s * GTM * GKP;
            unsigned* Bhd = Bhs + s * GTN * GKP;
            unsigned* Bld = Bls + s * GTN * GKP;
            #pragma unroll
            for (int i = 0; i < 4; i++) {
                int row = lrow + i * 64;
                unsigned w = row * GKP + (lch >> 1);
                cp16(&Ahd[w], &Ah[(size_t)(m0 + row) * K + k0 + lch]);
                cp16(&Ald[w], &Al[(size_t)(m0 + row) * K + k0 + lch]);
            }
            #pragma unroll
            for (int i = 0; i < 2; i++) {
                int row = lrow + i * 64;
                unsigned w = row * GKP + (lch >> 1);
                cp16(&Bhd[w], &Wh[(size_t)(n0 + row) * K + k0 + lch]);
                cp16(&Bld[w], &Wl[(size_t)(n0 + row) * K + k0 + lch]);
            }
            cp_commit();
        }

        const unsigned* Ahb = Ahs + (kt & 1) * GTM * GKP;
        const unsigned* Alb = Als + (kt & 1) * GTM * GKP;
        const unsigned* Bhb = Bhs + (kt & 1) * GTN * GKP;
        const unsigned* Blb = Bls + (kt & 1) * GTN * GKP;

        #pragma unroll
        for (int ks = 0; ks < 2; ks++) {
            const int kw = ks * 8 + tg;
            unsigned ah[4][4], al[4][4], bh[8][2], bl[8][2];
            #pragma unroll
            for (int mf = 0; mf < 4; mf++) {
                unsigned w = (wm * 64 + mf * 16 + g) * GKP + kw;
                ah[mf][0] = Ahb[w];
                ah[mf][1] = Ahb[w + 8 * GKP];
                ah[mf][2] = Ahb[w + 4];
                ah[mf][3] = Ahb[w + 8 * GKP + 4];
                al[mf][0] = Alb[w];
                al[mf][1] = Alb[w + 8 * GKP];
                al[mf][2] = Alb[w + 4];
                al[mf][3] = Alb[w + 8 * GKP + 4];
            }
            #pragma unroll
            for (int nf = 0; nf < 8; nf++) {
                unsigned w = (wn * 64 + nf * 8 + g) * GKP + kw;
                bh[nf][0] = Bhb[w];
                bh[nf][1] = Bhb[w + 4];
                bl[nf][0] = Blb[w];
                bl[nf][1] = Blb[w + 4];
            }
            #pragma unroll
            for (int mf = 0; mf < 4; mf++)
                #pragma unroll
                for (int nf = 0; nf < 8; nf++) {
                    mma_bf16(acc[mf][nf], ah[mf], bl[nf]);
                    mma_bf16(acc[mf][nf], al[mf], bh[nf]);
                    mma_bf16(acc[mf][nf], ah[mf], bh[nf]);
                }
        }
        __syncthreads();
    }

    // --- epilogue ---
    #pragma unroll
    for (int mf = 0; mf < 4; mf++) {
        #pragma unroll
        for (int nf = 0; nf < 8; nf++) {
            int row = m0 + wm * 64 + mf * 16 + g;
            int col = n0 + wn * 64 + nf * 8 + tg * 2;
            float b0 = bias[col], b1 = bias[col + 1];
            float x0 = (acc[mf][nf][0] + b0) * scale;
            float x1 = (acc[mf][nf][1] + b1) * scale;
            float x2 = (acc[mf][nf][2] + b0) * scale;
            float x3 = (acc[mf][nf][3] + b1) * scale;
            if (mode == 0) {
                *(float2*)&C[(size_t)row * N + col]       = make_float2(x0, x1);
                *(float2*)&C[(size_t)(row + 8) * N + col] = make_float2(x2, x3);
            } else {
                __nv_bfloat162 h0 = __floats2bfloat162_rn(x0, x1);
                __nv_bfloat162 h2 = __floats2bfloat162_rn(x2, x3);
                float2 f0 = __bfloat1622float2(h0);
                float2 f2 = __bfloat1622float2(h2);
                __nv_bfloat162 l0 = __floats2bfloat162_rn(x0 - f0.x, x1 - f0.y);
                __nv_bfloat162 l2 = __floats2bfloat162_rn(x2 - f2.x, x3 - f2.y);
                *(__nv_bfloat162*)&Ch[(size_t)row * N + col]       = h0;
                *(__nv_bfloat162*)&Ch[(size_t)(row + 8) * N + col] = h2;
                *(__nv_bfloat162*)&Cl[(size_t)row * N + col]       = l0;
                *(__nv_bfloat162*)&Cl[(size_t)(row + 8) * N + col] = l2;
            }
        }
    }
}

// ---------------------------------------------------------------------------
// bf16x3 tensor-core flash attention. Block: (b, h, 64-row q tile),
// 128 threads / 4 warps, 16 q-rows per warp. All operands bf16 hi/lo planes;
// Q pre-scaled by 1/sqrt(HD) in the projection epilogue. V pre-transposed.
// smem word pitch 36: frag addr (4g+tg) mod 32 covers all banks.
// ---------------------------------------------------------------------------
#define FW 36
#define FB_SMEM (8 * 64 * FW * 4)

__global__ __launch_bounds__(128) void flash_bf16(
    const __nv_bfloat16* __restrict__ Qh, const __nv_bfloat16* __restrict__ Ql,
    const __nv_bfloat16* __restrict__ Kh, const __nv_bfloat16* __restrict__ Kl,
    const __nv_bfloat16* __restrict__ Vh, const __nv_bfloat16* __restrict__ Vl,
    float* __restrict__ O)
{
    extern __shared__ unsigned su[];
    unsigned* Qhs = su;
    unsigned* Qls = su + 64 * FW;
    unsigned* Khs = su + 2 * 64 * FW;
    unsigned* Kls = su + 3 * 64 * FW;
    unsigned* Vhs = su + 4 * 64 * FW;
    unsigned* Vls = su + 5 * 64 * FW;
    unsigned* Phs = su + 6 * 64 * FW;
    unsigned* Pls = su + 7 * 64 * FW;

    const int qi = blockIdx.x;
    const int h  = blockIdx.y;
    const int b  = blockIdx.z;
    const int q0 = qi * 64;

    const int tid  = threadIdx.x;
    const int warp = tid >> 5, lane = tid & 31;
    const int g = lane >> 2, tg = lane & 3;

    const int lr  = tid >> 3;         // 0..15
    const int lcw = (tid & 7) * 4;    // word offset 0..28 (16B chunks)

    // Load Q hi/lo tiles [64][64 bf16] (Q already scaled by 0.125)
    #pragma unroll
    for (int it = 0; it < 4; it++) {
        int r = lr + it * 16;
        size_t gofs = ((size_t)b * SQ_ + q0 + r) * D_ + h * HD_ + lcw * 2;
        *(uint4*)&Qhs[r * FW + lcw] = *(const uint4*)&Qh[gofs];
        *(uint4*)&Qls[r * FW + lcw] = *(const uint4*)&Ql[gofs];
    }

    float m0 = -INFINITY, m1 = -INFINITY, l0 = 0.f, l1 = 0.f;
    float o[8][4];
    #pragma unroll
    for (int nf = 0; nf < 8; nf++)
        #pragma unroll
        for (int j = 0; j < 4; j++) o[nf][j] = 0.f;

    for (int kt = 0; kt <= qi; kt++) {
        const int k0 = kt * 64;
        __syncthreads();   // Q store (first iter) / prior-tile reads complete
        #pragma unroll
        for (int it = 0; it < 4; it++) {
            int r = lr + it * 16;
            size_t kofs = ((size_t)b * SK_ + k0 + r) * D_ + h * HD_ + lcw * 2;
            size_t vofs = ((size_t)b * D_ + h * HD_ + r) * SK_ + k0 + lcw * 2;
            *(uint4*)&Khs[r * FW + lcw] = *(const uint4*)&Kh[kofs];
            *(uint4*)&Kls[r * FW + lcw] = *(const uint4*)&Kl[kofs];
            *(uint4*)&Vhs[r * FW + lcw] = *(const uint4*)&Vh[vofs];
            *(uint4*)&Vls[r * FW + lcw] = *(const uint4*)&Vl[vofs];
        }
        __syncthreads();

        // ---- S = Q K^T (bf16x3) ----
        float c[8][4];
        #pragma unroll
        for (int nf = 0; nf < 8; nf++)
            #pragma unroll
            for (int j = 0; j < 4; j++) c[nf][j] = 0.f;

        #pragma unroll
        for (int ks = 0; ks < 4; ks++) {
            unsigned ah[4], al[4], bh[8][2], bl[8][2];
            unsigned w = (warp * 16 + g) * FW + ks * 8 + tg;
            ah[0] = Qhs[w];           al[0] = Qls[w];
            ah[1] = Qhs[w + 8 * FW];  al[1] = Qls[w + 8 * FW];
            ah[2] = Qhs[w + 4];       al[2] = Qls[w + 4];
            ah[3] = Qhs[w + 8 * FW + 4]; al[3] = Qls[w + 8 * FW + 4];
            #pragma unroll
            for (int nf = 0; nf < 8; nf++) {
                unsigned wb = (nf * 8 + g) * FW + ks * 8 + tg;
                bh[nf][0] = Khs[wb];     bh[nf][1] = Khs[wb + 4];
                bl[nf][0] = Kls[wb];     bl[nf][1] = Kls[wb + 4];
            }
            #pragma unroll
            for (int nf = 0; nf < 8; nf++) {
                mma_bf16(c[nf], ah, bl[nf]);
                mma_bf16(c[nf], al, bh[nf]);
                mma_bf16(c[nf], ah, bh[nf]);
            }
        }

        // ---- causal mask on diagonal tile ----
        if (kt == qi) {
            const int r0 = warp * 16 + g, r1 = r0 + 8;
            #pragma unroll
            for (int nf = 0; nf < 8; nf++) {
                int col0 = nf * 8 + tg * 2, col1 = col0 + 1;
                if (col0 > r0) c[nf][0] = -1e9f;
                if (col1 > r0) c[nf][1] = -1e9f;
                if (col0 > r1) c[nf][2] = -1e9f;
                if (col1 > r1) c[nf][3] = -1e9f;
            }
        }

        // ---- online softmax ----
        float rx0 = -INFINITY, rx1 = -INFINITY;
        #pragma unroll
        for (int nf = 0; nf < 8; nf++) {
            rx0 = fmaxf(rx0, fmaxf(c[nf][0], c[nf][1]));
            rx1 = fmaxf(rx1, fmaxf(c[nf][2], c[nf][3]));
        }
        #pragma unroll
        for (int off = 1; off <= 2; off <<= 1) {
            rx0 = fmaxf(rx0, __shfl_xor_sync(0xffffffffu, rx0, off));
            rx1 = fmaxf(rx1, __shfl_xor_sync(0xffffffffu, rx1, off));
        }
        float mn0 = fmaxf(m0, rx0), mn1 = fmaxf(m1, rx1);
        float corr0 = __expf(m0 - mn0), corr1 = __expf(m1 - mn1);
        m0 = mn0; m1 = mn1;

        float rs0 = 0.f, rs1 = 0.f;
        #pragma unroll
        for (int nf = 0; nf < 8; nf++) {
            c[nf][0] = __expf(c[nf][0] - mn0);
            c[nf][1] = __expf(c[nf][1] - mn0);
            c[nf][2] = __expf(c[nf][2] - mn1);
            c[nf][3] = __expf(c[nf][3] - mn1);
            rs0 += c[nf][0] + c[nf][1];
            rs1 += c[nf][2] + c[nf][3];
            // split P to bf16 hi/lo, store packed words (warp-private rows)
            __nv_bfloat162 h0 = __floats2bfloat162_rn(c[nf][0], c[nf][1]);
            __nv_bfloat162 h2 = __floats2bfloat162_rn(c[nf][2], c[nf][3]);
            float2 f0 = __bfloat1622float2(h0);
            float2 f2 = __bfloat1622float2(h2);
            __nv_bfloat162 pl0 = __floats2bfloat162_rn(c[nf][0] - f0.x, c[nf][1] - f0.y);
            __nv_bfloat162 pl2 = __floats2bfloat162_rn(c[nf][2] - f2.x, c[nf][3] - f2.y);
            unsigned wp = (warp * 16 + g) * FW + nf * 4 + tg;
            Phs[wp]          = *(unsigned*)&h0;
            Pls[wp]          = *(unsigned*)&pl0;
            Phs[wp + 8 * FW] = *(unsigned*)&h2;
            Pls[wp + 8 * FW] = *(unsigned*)&pl2;
        }
        #pragma unroll
        for (int off = 1; off <= 2; off <<= 1) {
            rs0 += __shfl_xor_sync(0xffffffffu, rs0, off);
            rs1 += __shfl_xor_sync(0xffffffffu, rs1, off);
        }
        l0 = l0 * corr0 + rs0;
        l1 = l1 * corr1 + rs1;
        #pragma unroll
        for (int nf = 0; nf < 8; nf++) {
            o[nf][0] *= corr0; o[nf][1] *= corr0;
            o[nf][2] *= corr1; o[nf][3] *= corr1;
        }
        __syncwarp();

        // ---- O += P V (bf16x3); B operand from transposed V planes ----
        #pragma unroll
        for (int ks = 0; ks < 4; ks++) {
            unsigned ah[4], al[4], bh[8][2], bl[8][2];
            unsigned w = (warp * 16 + g) * FW + ks * 8 + tg;
            ah[0] = Phs[w];           al[0] = Pls[w];
            ah[1] = Phs[w + 8 * FW];  al[1] = Pls[w + 8 * FW];
            ah[2] = Phs[w + 4];       al[2] = Pls[w + 4];
            ah[3] = Phs[w + 8 * FW + 4]; al[3] = Pls[w + 8 * FW + 4];
            #pragma unroll
            for (int nf = 0; nf < 8; nf++) {
                unsigned wb = (nf * 8 + g) * FW + ks * 8 + tg;
                bh[nf][0] = Vhs[wb];     bh[nf][1] = Vhs[wb + 4];
                bl[nf][0] = Vls[wb];     bl[nf][1] = Vls[wb + 4];
            }
            #pragma unroll
            for (int nf = 0; nf < 8; nf++) {
                mma_bf16(o[nf], ah, bl[nf]);
                mma_bf16(o[nf], al, bh[nf]);
                mma_bf16(o[nf], ah, bh[nf]);
            }
        }
    }

    // ---- epilogue ----
    float inv0 = 1.f / l0, inv1 = 1.f / l1;
    float* Obase = O + ((size_t)b * SQ_ + q0 + warp * 16 + g) * D_ + h * HD_;
    #pragma unroll
    for (int nf = 0; nf < 8; nf++) {
        int col = nf * 8 + tg * 2;
        *(float2*)&Obase[col] =
            make_float2(o[nf][0] * inv0, o[nf][1] * inv0);
        *(float2*)&Obase[(size_t)8 * D_ + col] =
            make_float2(o[nf][2] * inv1, o[nf][3] * inv1);
    }
}

// ---------------------------------------------------------------------------
extern "C" void kernel_launch(void* const* d_in, const int* in_sizes, int n_in,
                              void* d_out, int out_size)
{
    const float* query = (const float*)d_in[0];
    const float* key   = (const float*)d_in[1];
    const float* value = (const float*)d_in[2];
    const float* Wq = (const float*)d_in[5];
    const float* bq = (const float*)d_in[6];
    const float* Wk = (const float*)d_in[7];
    const float* bk = (const float*)d_in[8];
    const float* Wv = (const float*)d_in[9];
    const float* bv = (const float*)d_in[10];
    const float* Wo = (const float*)d_in[11];
    const float* bo = (const float*)d_in[12];
    float* out = (float*)d_out;

    float *v, *attn;
    __nv_bfloat16 *xh, *xl, *wh, *wl, *qh, *ql, *kh, *kl, *vth, *vtl;
    cudaGetSymbolAddress((void**)&v,    g_v);
    cudaGetSymbolAddress((void**)&attn, g_attn);
    cudaGetSymbolAddress((void**)&xh,   g_xh);
    cudaGetSymbolAddress((void**)&xl,   g_xl);
    cudaGetSymbolAddress((void**)&wh,   g_wh);
    cudaGetSymbolAddress((void**)&wl,   g_wl);
    cudaGetSymbolAddress((void**)&qh,   g_qh);
    cudaGetSymbolAddress((void**)&ql,   g_ql);
    cudaGetSymbolAddress((void**)&kh,   g_kh);
    cudaGetSymbolAddress((void**)&kl,   g_kl);
    cudaGetSymbolAddress((void**)&vth,  g_vth);
    cudaGetSymbolAddress((void**)&vtl,  g_vtl);

    const int M = B_ * SQ_;
    const int NX = M * D_;
    const int NW = D_ * D_;

    static int attr_done = 0;
    if (!attr_done) {
        cudaFuncSetAttribute(gemm_bf16x3,
                             cudaFuncAttributeMaxDynamicSharedMemorySize, GEMMB_SMEM);
        cudaFuncSetAttribute(flash_bf16,
                             cudaFuncAttributeMaxDynamicSharedMemorySize, FB_SMEM);
        attr_done = 1;
    }

    dim3 ggrid(D_ / GTN, M / GTM);
    const int SPX = NX / 4 / 256;
    const int SPW = NW / 4 / 256;

    // Q projection -> bf16 planes, pre-scaled by 1/sqrt(HD)
    split_kernel<<<SPX, 256>>>(query, xh, xl, NX);
    split_kernel<<<SPW, 256>>>(Wq, wh, wl, NW);
    gemm_bf16x3<<<ggrid, 256, GEMMB_SMEM>>>(xh, xl, wh, wl, bq,
                                            nullptr, qh, ql, 0.125f, 1, M, D_, D_);
    // K projection -> bf16 planes
    split_kernel<<<SPX, 256>>>(key, xh, xl, NX);
    split_kernel<<<SPW, 256>>>(Wk, wh, wl, NW);
    gemm_bf16x3<<<ggrid, 256, GEMMB_SMEM>>>(xh, xl, wh, wl, bk,
                                            nullptr, kh, kl, 1.0f, 1, M, D_, D_);
    // V projection -> fp32, then transpose+split
    split_kernel<<<SPX, 256>>>(value, xh, xl, NX);
    split_kernel<<<SPW, 256>>>(Wv, wh, wl, NW);
    gemm_bf16x3<<<ggrid, 256, GEMMB_SMEM>>>(xh, xl, wh, wl, bv,
                                            v, nullptr, nullptr, 1.0f, 0, M, D_, D_);
    transpose_split<<<dim3(D_ / 32, SK_ / 32, B_), dim3(32, 8)>>>(v, vth, vtl);

    flash_bf16<<<dim3(SQ_ / 64, H_, B_), 128, FB_SMEM>>>(qh, ql, kh, kl, vth, vtl, attn);

    // Output projection -> fp32 out
    split_kernel<<<SPX, 256>>>(attn, xh, xl, NX);
    split_kernel<<<SPW, 256>>>(Wo, wh, wl, NW);
    gemm_bf16x3<<<ggrid, 256, GEMMB_SMEM>>>(xh, xl, wh, wl, bo,
                                            out, nullptr, nullptr, 1.0f, 0, M, D_, D_);
}